// round 17
// baseline (speedup 1.0000x reference)
#include <cuda_runtime.h>
#include <cuda_bf16.h>
#include <math_constants.h>
#include <cstdint>

// Problem shape (fixed by the reference)
#define L_DIM 1024
#define B_DIM 64
#define H_DIM 1024
#define N_ROWS (L_DIM * B_DIM)           // flat rows, b-major: r = b*1024 + l

#define G_CTAS 296                       // 148 SMs x 2 CTAs (occ 2) -> balanced
#define WARPS_PER_BLOCK 8
#define HV 8                             // float4 vectors per thread (H/128)
#define MAXC 8                           // max contributing slots per b
#define PF_ROWS WARPS_PER_BLOCK          // prefetch distance: 1 warp-iteration

// Scratch: one partial per (cta, segment). 592 slots x 4 KB ~= 2.4 MB.
__device__ float g_ctx[2 * G_CTAS * H_DIM];
__device__ float g_m[2 * G_CTAS];
__device__ float g_d[2 * G_CTAS];
__device__ int   g_tag[2 * G_CTAS];      // b+1 of the partial in this slot
__device__ int   g_rows[B_DIM];          // rows accumulated per b; reset by combiner

__device__ __forceinline__ void prefetch_l2(const void* p) {
    asm volatile("prefetch.global.L2 [%0];" :: "l"(p));
}

// ---------------------------------------------------------------------------
// R16's hot loop (branch-free softmax, __ldcs, L2-prefetch d=1) on a flat,
// perfectly balanced 296-CTA partition. block 256 (8 warps), occ 2.
// ---------------------------------------------------------------------------
__global__ __launch_bounds__(256, 2)
void attn_fused(const float* __restrict__ enc,   // [L, B, H]
                const float* __restrict__ dec,   // [1, B, H]
                float* __restrict__ out)         // [B, H]
{
    const int cta  = blockIdx.x;
    const int warp = threadIdx.x >> 5;
    const int lane = threadIdx.x & 31;

    __shared__ float s_acc[WARPS_PER_BLOCK][H_DIM];   // 32 KB
    __shared__ float s_m[WARPS_PER_BLOCK];
    __shared__ float s_d[WARPS_PER_BLOCK];
    __shared__ float s_scale[WARPS_PER_BLOCK];
    __shared__ int   s_is_last;

    const int r0 = (int)(((long long)cta * N_ROWS) / G_CTAS);
    const int r1 = (int)(((long long)(cta + 1) * N_ROWS) / G_CTAS);
    const int b0   = r0 >> 10;
    const int bend = (r1 - 1) >> 10;
    const int nseg = (bend > b0) ? 2 : 1;

    for (int seg = 0; seg < nseg; seg++) {
        const int b  = b0 + seg;
        const int s0 = max(r0, b << 10);
        const int s1 = min(r1, (b + 1) << 10);
        const int seg_rows = s1 - s0;

        // Decoder slice in registers: h = k*128 + lane*4
        const float4* dec4 = reinterpret_cast<const float4*>(dec + (size_t)b * H_DIM);
        float4 dv[HV];
#pragma unroll
        for (int k = 0; k < HV; k++) dv[k] = dec4[k * 32 + lane];

        float4 acc[HV];
#pragma unroll
        for (int k = 0; k < HV; k++) acc[k] = make_float4(0.f, 0.f, 0.f, 0.f);
        float m = -CUDART_INF_F;
        float d = 0.f;

        // Warm: prefetch the first row for this warp.
        {
            const int rw = min(s0 + warp, s1 - 1);
            const char* pw = reinterpret_cast<const char*>(
                enc + ((size_t)(rw & 1023) * B_DIM + b) * H_DIM);
            prefetch_l2(pw + lane * 128);
        }

        for (int r = s0 + warp; r < s1; r += WARPS_PER_BLOCK) {
            // ---- prefetch the row 1 iteration ahead (1 inst, 0 regs) ----
            {
                const int rp = min(r + PF_ROWS, s1 - 1);
                const char* pp = reinterpret_cast<const char*>(
                    enc + ((size_t)(rp & 1023) * B_DIM + b) * H_DIM);
                prefetch_l2(pp + lane * 128);
            }

            const int l = r & 1023;
            const float4* e4 =
                reinterpret_cast<const float4*>(enc + ((size_t)l * B_DIM + b) * H_DIM);
            float4 ev[HV];
#pragma unroll
            for (int k = 0; k < HV; k++) ev[k] = __ldcs(&e4[k * 32 + lane]);

            // dot(e, dec): per-thread partial, warp butterfly reduce
            float sc = 0.f;
#pragma unroll
            for (int k = 0; k < HV; k++) {
                sc = fmaf(ev[k].x, dv[k].x, sc);
                sc = fmaf(ev[k].y, dv[k].y, sc);
                sc = fmaf(ev[k].z, dv[k].z, sc);
                sc = fmaf(ev[k].w, dv[k].w, sc);
            }
#pragma unroll
            for (int off = 16; off > 0; off >>= 1)
                sc += __shfl_xor_sync(0xffffffffu, sc, off);

            // branch-free online softmax update
            float nm    = fmaxf(m, sc);
            float alpha = __expf(m - nm);   // 0 on first iter (m = -inf)
            float w     = __expf(sc - nm);
            d = d * alpha + w;
            m = nm;
#pragma unroll
            for (int k = 0; k < HV; k++) {
                acc[k].x = fmaf(w, ev[k].x, acc[k].x * alpha);
                acc[k].y = fmaf(w, ev[k].y, acc[k].y * alpha);
                acc[k].z = fmaf(w, ev[k].z, acc[k].z * alpha);
                acc[k].w = fmaf(w, ev[k].w, acc[k].w * alpha);
            }
        }

        // ---- in-block flash combine of the 8 warp partials ----
        __syncthreads();   // protect s_acc reuse across segments
#pragma unroll
        for (int k = 0; k < HV; k++)
            *reinterpret_cast<float4*>(&s_acc[warp][k * 128 + lane * 4]) = acc[k];
        if (lane == 0) { s_m[warp] = m; s_d[warp] = d; }
        __syncthreads();

        const int slot = 2 * cta + seg;
        if (threadIdx.x == 0) {
            float M = -CUDART_INF_F;
#pragma unroll
            for (int w = 0; w < WARPS_PER_BLOCK; w++)
                if (s_d[w] > 0.f) M = fmaxf(M, s_m[w]);
            float D = 0.f;
#pragma unroll
            for (int w = 0; w < WARPS_PER_BLOCK; w++) {
                float sc = (s_d[w] > 0.f) ? __expf(s_m[w] - M) : 0.f;
                s_scale[w] = sc;
                D += s_d[w] * sc;
            }
            g_m[slot] = M;
            g_d[slot] = D;
            g_tag[slot] = b + 1;
        }
        __syncthreads();

        {
            const int h = threadIdx.x * 4;
            float4 sum = make_float4(0.f, 0.f, 0.f, 0.f);
#pragma unroll
            for (int w = 0; w < WARPS_PER_BLOCK; w++) {
                float sc = s_scale[w];
                float4 v = *reinterpret_cast<const float4*>(&s_acc[w][h]);
                sum.x = fmaf(sc, v.x, sum.x);
                sum.y = fmaf(sc, v.y, sum.y);
                sum.z = fmaf(sc, v.z, sum.z);
                sum.w = fmaf(sc, v.w, sum.w);
            }
            *reinterpret_cast<float4*>(&g_ctx[(size_t)slot * H_DIM + h]) = sum;
        }

        // ---- arrival: count rows; the CTA reaching 1024 combines b ----
        __threadfence();
        if (threadIdx.x == 0) {
            int old = atomicAdd(&g_rows[b], seg_rows);
            s_is_last = (old + seg_rows == L_DIM) ? 1 : 0;
        }
        __syncthreads();
        if (!s_is_last) continue;

        __threadfence();   // order reads of peers' partials after the atomic

        // Candidate contributor CTAs form a contiguous window around b.
        int ilo = max(0, (int)(((long long)(b << 10) * G_CTAS) / N_ROWS) - 1);
        int ihi = min(G_CTAS - 1,
                      (int)(((long long)((b + 1) << 10) * G_CTAS) / N_ROWS) + 1);

        int slots[MAXC];
        int nc = 0;
        for (int i = ilo; i <= ihi && nc < MAXC; i++) {
#pragma unroll
            for (int sg = 0; sg < 2; sg++) {
                int sl = 2 * i + sg;
                if (g_tag[sl] == b + 1 && nc < MAXC) slots[nc++] = sl;
            }
        }

        float M = -CUDART_INF_F;
        for (int p = 0; p < nc; p++) M = fmaxf(M, g_m[slots[p]]);
        float D = 0.f;
        float scl[MAXC];
        for (int p = 0; p < nc; p++) {
            scl[p] = __expf(g_m[slots[p]] - M);
            D += g_d[slots[p]] * scl[p];
        }
        const float invD = 1.f / D;

        {
            const int h = threadIdx.x * 4;
            float4 sum = make_float4(0.f, 0.f, 0.f, 0.f);
            for (int p = 0; p < nc; p++) {
                const float sc = scl[p] * invD;
                float4 v = *reinterpret_cast<const float4*>(
                    &g_ctx[(size_t)slots[p] * H_DIM + h]);
                sum.x = fmaf(sc, v.x, sum.x);
                sum.y = fmaf(sc, v.y, sum.y);
                sum.z = fmaf(sc, v.z, sum.z);
                sum.w = fmaf(sc, v.w, sum.w);
            }
            *reinterpret_cast<float4*>(&out[(size_t)b * H_DIM + h]) = sum;
        }

        if (threadIdx.x == 0) g_rows[b] = 0;   // reset for next graph replay
    }
}

// ---------------------------------------------------------------------------
extern "C" void kernel_launch(void* const* d_in, const int* in_sizes, int n_in,
                              void* d_out, int out_size)
{
    const float* enc = (const float*)d_in[0];   // [1024, 64, 1024]
    const float* dec = (const float*)d_in[1];   // [1, 64, 1024]
    float* out = (float*)d_out;                 // [64, 1024]

    attn_fused<<<G_CTAS, 256>>>(enc, dec, out);
}